// round 14
// baseline (speedup 1.0000x reference)
#include <cuda_runtime.h>
#include <cuda_bf16.h>
#include <cstdint>
#include <cstddef>

// Problem constants
#define BB    2
#define NN    2048
#define DIMM  512
#define HH    8
#define DHH   64
#define NQ    513          // distinct effective query rows per head (q[i] = q[i % 513])
#define G     16           // B*H
#define ROWS  4096         // B*N
#define FROWS 640          // padded NQ for flash partials (5 * 128)
#define NSPLIT 8           // flash split-j factor

// r = exp(-1/e)
#define RDEC 0.69220062755534637f

typedef __nv_bfloat16  bf16;
typedef __nv_bfloat162 bf162;

// ---------------- scratch (static device arrays; no allocation) ----------------
__device__ __align__(256) float g_t[(size_t)ROWS * 512];          // t quarter fp32
__device__ __align__(256) float g_O1[(size_t)1152 * 512];         // O1proj fp32

__device__ __align__(256) bf16 g_xh[(size_t)ROWS * DIMM];         // x planes
__device__ __align__(256) bf16 g_xl[(size_t)ROWS * DIMM];
__device__ __align__(256) bf16 g_Wqth[(size_t)2048 * DIMM];       // W_qkv^T planes
__device__ __align__(256) bf16 g_Wqtl[(size_t)2048 * DIMM];
__device__ __align__(256) bf16 g_Wo1th[(size_t)512 * 512];        // W_out^T (out1 rows) planes
__device__ __align__(256) bf16 g_Wo1tl[(size_t)512 * 512];
__device__ __align__(256) bf16 g_Wo2th[(size_t)512 * 512];        // W_out^T (out2 rows) planes
__device__ __align__(256) bf16 g_Wo2tl[(size_t)512 * 512];
__device__ __align__(256) bf16 g_qkh[(size_t)ROWS * 1024];        // Q/K planes (cols 0..1023)
__device__ __align__(256) bf16 g_qkl[(size_t)ROWS * 1024];
__device__ __align__(256) bf16 g_vh[(size_t)ROWS * 512];          // V planes [row][h*64+c]
__device__ __align__(256) bf16 g_vl[(size_t)ROWS * 512];
__device__ __align__(256) bf16 g_o1h[(size_t)1152 * 512];         // combine out planes
__device__ __align__(256) bf16 g_o1l[(size_t)1152 * 512];
__device__ __align__(256) bf16 g_o2h[(size_t)ROWS * 512];         // scan out planes
__device__ __align__(256) bf16 g_o2l[(size_t)ROWS * 512];

// flash split-j partials
__device__ __align__(256) float g_pO[(size_t)NSPLIT * G * FROWS * DHH];
__device__ __align__(256) float g_pM[NSPLIT * G * FROWS];
__device__ __align__(256) float g_pL[NSPLIT * G * FROWS];

// ======================= portable PTX helpers =======================
__device__ __forceinline__ uint32_t smem_u32(const void* p) {
    uint32_t a;
    asm("{ .reg .u64 t; cvta.to.shared.u64 t, %1; cvt.u32.u64 %0, t; }" : "=r"(a) : "l"(p));
    return a;
}
__device__ __forceinline__ void ldsm_x4(uint32_t* f, uint32_t addr) {
    asm volatile("ldmatrix.sync.aligned.m8n8.x4.shared.b16 {%0,%1,%2,%3}, [%4];"
                 : "=r"(f[0]), "=r"(f[1]), "=r"(f[2]), "=r"(f[3]) : "r"(addr));
}
__device__ __forceinline__ void ldsm_x4_t(uint32_t* f, uint32_t addr) {
    asm volatile("ldmatrix.sync.aligned.m8n8.x4.trans.shared.b16 {%0,%1,%2,%3}, [%4];"
                 : "=r"(f[0]), "=r"(f[1]), "=r"(f[2]), "=r"(f[3]) : "r"(addr));
}
__device__ __forceinline__ void mma16(float* c, const uint32_t* a, const uint32_t* b) {
    asm volatile("mma.sync.aligned.m16n8k16.row.col.f32.bf16.bf16.f32 "
                 "{%0,%1,%2,%3}, {%4,%5,%6,%7}, {%8,%9}, {%0,%1,%2,%3};"
                 : "+f"(c[0]), "+f"(c[1]), "+f"(c[2]), "+f"(c[3])
                 : "r"(a[0]), "r"(a[1]), "r"(a[2]), "r"(a[3]), "r"(b[0]), "r"(b[1]));
}
#define CP_ASYNC_COMMIT() asm volatile("cp.async.commit_group;")
#define CP_ASYNC_WAIT(n)  asm volatile("cp.async.wait_group %0;" :: "n"(n))
#define CP_ASYNC16(dst, src) \
    asm volatile("cp.async.cg.shared.global [%0], [%1], 16;" :: "r"(dst), "l"(src))
#define CP_ASYNC16Z(dst, src, gz) \
    asm volatile("cp.async.cg.shared.global [%0], [%1], 16, %2;" :: "r"(dst), "l"(src), "r"(gz))

__device__ __forceinline__ void bsplit(float v, bf16& h, bf16& l) {
    h = __float2bfloat16(v);
    l = __float2bfloat16(v - __bfloat162float(h));
}
__device__ __forceinline__ uint32_t pack_bf(float lo, float hi) {
    bf162 t; t.x = __float2bfloat16(lo); t.y = __float2bfloat16(hi);
    return *(uint32_t*)&t;
}

// interleaved-line SMEM layout for BK=32 (64B rows): 2 rows per 128B line
__device__ __forceinline__ uint32_t tpos(int r, int ch) {
    return ((uint32_t)(r >> 1) << 7) |
           ((uint32_t)((((r & 1) << 2) | ch) ^ ((r >> 1) & 7)) << 4);
}
// full-line layout for 128B rows (64 bf16): chunk ch in 0..7
__device__ __forceinline__ uint32_t fpos(int r, int ch) {
    return ((uint32_t)r << 7) | ((uint32_t)(ch ^ (r & 7)) << 4);
}

#define STAGES 3

// =====================================================================
// bf16x3 mma.sync GEMM: C[M,N] = A[M,K] @ B[N,K]^T (+extras)
// A/B as (hi, lo) bf16 planes, K-major.  CTA BM x BN, 8 warps (4m x 2n).
// __launch_bounds__(256, 2): cap 128 regs -> 2 CTAs/SM.
// MODE 0: plain fp32 C (+bias if given).
// MODE 1: qkvt producer (Q region only rows%2048<640; fused plane epilogues).
// MODE 5: final out.  C = acc + bias[cg] + O1proj[b*513 + i%513][cg].
// =====================================================================
template<int BM, int BN, int MODE>
__global__ __launch_bounds__(256, 2) void bmma_gemm(
    const bf16* __restrict__ Ah, const bf16* __restrict__ Al, int lda,
    const bf16* __restrict__ Bh, const bf16* __restrict__ Bl, int ldb,
    float* __restrict__ C, int ldc,
    int M, int K, const float* __restrict__ bias)
{
    constexpr int MT     = BM / 64;
    constexpr int NTILES = BN / 16;
    constexpr int APL = BM * 64;
    constexpr int BPL = BN * 64;
    constexpr int STAGE = 2 * (APL + BPL);

    int row0 = blockIdx.y * BM;
    int col0 = blockIdx.x * BN;
    if (MODE == 1) {
        if (col0 < 512 && (row0 & 2047) >= FROWS) return;   // Q region: 640 rows/batch
    }

    extern __shared__ __align__(1024) char smem[];
    uint32_t sbase = smem_u32(smem);
    int tid = threadIdx.x, wid = tid >> 5, lane = tid & 31;

    auto load_stage = [&](int stage, int k0) {
        uint32_t sb = sbase + stage * STAGE;
#pragma unroll
        for (int i = 0; i < BM * 4 / 256; ++i) {
            int id = tid + i * 256;
            int r = id >> 2, ch = id & 3;
            uint32_t pos = tpos(r, ch);
            const bf16* sh = Ah + (size_t)(row0 + r) * lda + k0 + ch * 8;
            const bf16* sl = Al + (size_t)(row0 + r) * lda + k0 + ch * 8;
            uint32_t gz = (row0 + r < M) ? 16u : 0u;
            CP_ASYNC16Z(sb + pos, sh, gz);
            CP_ASYNC16Z(sb + APL + pos, sl, gz);
        }
#pragma unroll
        for (int i = 0; i < BN * 4 / 256; ++i) {
            int id = tid + i * 256;
            int r = id >> 2, ch = id & 3;
            uint32_t pos = tpos(r, ch);
            const bf16* sh = Bh + (size_t)(col0 + r) * ldb + k0 + ch * 8;
            const bf16* sl = Bl + (size_t)(col0 + r) * ldb + k0 + ch * 8;
            CP_ASYNC16(sb + 2 * APL + pos, sh);
            CP_ASYNC16(sb + 2 * APL + BPL + pos, sl);
        }
    };

    int NT = K >> 5;
#pragma unroll
    for (int s = 0; s < STAGES - 1; ++s) {
        if (s < NT) load_stage(s, s * 32);
        CP_ASYNC_COMMIT();
    }

    int wm = wid & 3, wn = wid >> 2;
    int mbase = wm * (BM / 4);
    int nbase = wn * (BN / 2);

    float acc[MT][NTILES][4];
#pragma unroll
    for (int mt = 0; mt < MT; ++mt)
#pragma unroll
        for (int nt = 0; nt < NTILES; ++nt)
#pragma unroll
            for (int j = 0; j < 4; ++j) acc[mt][nt][j] = 0.f;

    for (int t = 0; t < NT; ++t) {
        CP_ASYNC_WAIT(STAGES - 2);
        __syncthreads();
        if (t + STAGES - 1 < NT)
            load_stage((t + STAGES - 1) % STAGES, (t + STAGES - 1) * 32);
        CP_ASYNC_COMMIT();

        uint32_t sb = sbase + (t % STAGES) * STAGE;
#pragma unroll
        for (int kk = 0; kk < 2; ++kk) {
            uint32_t ah[MT][4], al[MT][4];
#pragma unroll
            for (int mt = 0; mt < MT; ++mt) {
                int r = mbase + mt * 16 + (lane & 15);
                int ch = kk * 2 + (lane >> 4);
                uint32_t pos = tpos(r, ch);
                ldsm_x4(ah[mt], sb + pos);
                ldsm_x4(al[mt], sb + APL + pos);
            }
            uint32_t bh[NTILES][2], bl[NTILES][2];
#pragma unroll
            for (int p = 0; p < NTILES / 2; ++p) {
                int r = nbase + p * 16 + ((lane >> 4) << 3) + (lane & 7);
                int ch = kk * 2 + ((lane >> 3) & 1);
                uint32_t pos = tpos(r, ch);
                uint32_t f[4];
                ldsm_x4(f, sb + 2 * APL + pos);
                bh[2 * p][0] = f[0]; bh[2 * p][1] = f[1];
                bh[2 * p + 1][0] = f[2]; bh[2 * p + 1][1] = f[3];
                ldsm_x4(f, sb + 2 * APL + BPL + pos);
                bl[2 * p][0] = f[0]; bl[2 * p][1] = f[1];
                bl[2 * p + 1][0] = f[2]; bl[2 * p + 1][1] = f[3];
            }
#pragma unroll
            for (int mt = 0; mt < MT; ++mt)
#pragma unroll
                for (int nt = 0; nt < NTILES; ++nt) {
                    mma16(acc[mt][nt], ah[mt], bh[nt]);
                    mma16(acc[mt][nt], ah[mt], bl[nt]);
                    mma16(acc[mt][nt], al[mt], bh[nt]);
                }
        }
    }
    CP_ASYNC_WAIT(0);

    int cr = lane >> 2, cc = (lane & 3) * 2;
#pragma unroll
    for (int mt = 0; mt < MT; ++mt) {
        int rgb = row0 + mbase + mt * 16 + cr;
#pragma unroll
        for (int nt = 0; nt < NTILES; ++nt) {
            int cg = col0 + nbase + nt * 8 + cc;
#pragma unroll
            for (int half = 0; half < 2; ++half) {
                int rg = rgb + half * 8;
                if (rg >= M) continue;
                float vx = acc[mt][nt][half * 2];
                float vy = acc[mt][nt][half * 2 + 1];
                if (MODE == 0) {
                    if (bias) {
                        float2 b2 = *(const float2*)(bias + cg);
                        vx += b2.x; vy += b2.y;
                    }
                    *(float2*)(C + (size_t)rg * ldc + cg) = make_float2(vx, vy);
                } else if (MODE == 5) {
                    float2 b2 = *(const float2*)(bias + cg);
                    int b = rg >> 11, i = rg & 2047;
                    int i513 = i % 513;
                    float2 o1 = *(const float2*)&g_O1[(size_t)(b * 513 + i513) * 512 + cg];
                    *(float2*)(C + (size_t)rg * ldc + cg) =
                        make_float2(vx + b2.x + o1.x, vy + b2.y + o1.y);
                } else { // MODE 1
                    if (cg < 1024) {
                        bf16 hx, lx, hy, ly;
                        bsplit(vx, hx, lx); bsplit(vy, hy, ly);
                        bf162 hh; hh.x = hx; hh.y = hy;
                        bf162 ll; ll.x = lx; ll.y = ly;
                        *(bf162*)&g_qkh[(size_t)rg * 1024 + cg] = hh;
                        *(bf162*)&g_qkl[(size_t)rg * 1024 + cg] = ll;
                    } else if (cg < 1536) {
                        bf16 hx, lx, hy, ly;
                        bsplit(vx, hx, lx); bsplit(vy, hy, ly);
                        bf162 hh; hh.x = hx; hh.y = hy;
                        bf162 ll; ll.x = lx; ll.y = ly;
                        *(bf162*)&g_vh[(size_t)rg * 512 + cg - 1024] = hh;
                        *(bf162*)&g_vl[(size_t)rg * 512 + cg - 1024] = ll;
                    } else {
                        *(float2*)&g_t[(size_t)rg * 512 + cg - 1536] = make_float2(vx, vy);
                    }
                }
            }
        }
    }
}

// =====================================================================
// Fused flash attention: S = 0.125 * Q K^T, online softmax, O = P V.
// grid (NSPLIT, 5, 16), 8 warps.  Q smem region reused by KV stages
// (64 KB total) + reg cap -> 2 CTAs/SM.
// =====================================================================
__global__ __launch_bounds__(256, 2) void flash_kernel()
{
    constexpr int JT = 2048 / (NSPLIT * 64);     // j-tiles per split
    extern __shared__ __align__(1024) char smem[];
    uint32_t sb = smem_u32(smem);

    int split = blockIdx.x, mtile = blockIdx.y, g = blockIdx.z;
    int b = g >> 3, h = g & 7;
    int row0 = mtile * 128;
    int tid = threadIdx.x, wid = tid >> 5, lane = tid & 31;

    const bf16* Qh = g_qkh + (size_t)b * 2048 * 1024 + h * 64;
    const bf16* Ql = g_qkl + (size_t)b * 2048 * 1024 + h * 64;
    const bf16* Kh = Qh + 512;
    const bf16* Kl = Ql + 512;
    const bf16* Vh = g_vh + (size_t)b * 2048 * 512 + h * 64;
    const bf16* Vl = g_vl + (size_t)b * 2048 * 512 + h * 64;

    // ---- Q tile load into stage-0 region (reused by KV afterwards) ----
    const uint32_t sQh = sb, sQl = sb + 16384;
#pragma unroll
    for (int i = 0; i < 4; ++i) {
        int id = tid + i * 256;
        int r = id >> 3, ch = id & 7;
        uint32_t pos = fpos(r, ch);
        uint32_t gz = (row0 + r < NQ) ? 16u : 0u;
        CP_ASYNC16Z(sQh + pos, Qh + (size_t)(row0 + r) * 1024 + ch * 8, gz);
        CP_ASYNC16Z(sQl + pos, Ql + (size_t)(row0 + r) * 1024 + ch * 8, gz);
    }
    CP_ASYNC_COMMIT();
    CP_ASYNC_WAIT(0);
    __syncthreads();

    // ---- Q fragments (held for whole loop) ----
    uint32_t qh[4][4], ql[4][4];
#pragma unroll
    for (int kk = 0; kk < 4; ++kk) {
        int r = wid * 16 + (lane & 15);
        uint32_t pos = fpos(r, 2 * kk + (lane >> 4));
        ldsm_x4(qh[kk], sQh + pos);
        ldsm_x4(ql[kk], sQl + pos);
    }
    __syncthreads();   // all warps done reading Q before KV overwrites

    int j0 = split * (2048 / NSPLIT);
    auto load_kv = [&](int stage, int jt) {
        uint32_t kb = sb + stage * 32768;
        int jb = j0 + jt * 64;
#pragma unroll
        for (int i = 0; i < 2; ++i) {
            int id = tid + i * 256;
            int r = id >> 3, ch = id & 7;
            uint32_t pos = fpos(r, ch);
            CP_ASYNC16(kb + pos,         Kh + (size_t)(jb + r) * 1024 + ch * 8);
            CP_ASYNC16(kb + 8192 + pos,  Kl + (size_t)(jb + r) * 1024 + ch * 8);
            CP_ASYNC16(kb + 16384 + pos, Vh + (size_t)(jb + r) * 512 + ch * 8);
            CP_ASYNC16(kb + 24576 + pos, Vl + (size_t)(jb + r) * 512 + ch * 8);
        }
    };
    load_kv(0, 0);
    CP_ASYNC_COMMIT();
    CP_ASYNC_WAIT(0);
    __syncthreads();

    float mr[2] = {-1e30f, -1e30f};
    float lr[2] = {0.f, 0.f};
    float oacc[8][4];
#pragma unroll
    for (int nt = 0; nt < 8; ++nt)
#pragma unroll
        for (int j = 0; j < 4; ++j) oacc[nt][j] = 0.f;

    for (int t = 0; t < JT; ++t) {
        if (t + 1 < JT) load_kv((t + 1) & 1, t + 1);
        CP_ASYNC_COMMIT();

        uint32_t kb = sb + (t & 1) * 32768;

        // ---- S = Q K^T (bf16x3), fragments per tile-pair ----
        float sacc[8][4];
#pragma unroll
        for (int nt = 0; nt < 8; ++nt)
#pragma unroll
            for (int j = 0; j < 4; ++j) sacc[nt][j] = 0.f;
#pragma unroll
        for (int kk = 0; kk < 4; ++kk) {
#pragma unroll
            for (int p = 0; p < 4; ++p) {
                int r = p * 16 + ((lane >> 4) << 3) + (lane & 7);
                uint32_t pos = fpos(r, 2 * kk + ((lane >> 3) & 1));
                uint32_t fh[4], fl[4];
                ldsm_x4(fh, kb + pos);
                ldsm_x4(fl, kb + 8192 + pos);
                uint32_t b0h[2] = {fh[0], fh[1]}, b1h[2] = {fh[2], fh[3]};
                uint32_t b0l[2] = {fl[0], fl[1]}, b1l[2] = {fl[2], fl[3]};
                mma16(sacc[2 * p],     qh[kk], b0h);
                mma16(sacc[2 * p],     qh[kk], b0l);
                mma16(sacc[2 * p],     ql[kk], b0h);
                mma16(sacc[2 * p + 1], qh[kk], b1h);
                mma16(sacc[2 * p + 1], qh[kk], b1l);
                mma16(sacc[2 * p + 1], ql[kk], b1h);
            }
        }

        // ---- scale + online softmax ----
#pragma unroll
        for (int nt = 0; nt < 8; ++nt)
#pragma unroll
            for (int j = 0; j < 4; ++j) sacc[nt][j] *= 0.125f;

#pragma unroll
        for (int hr = 0; hr < 2; ++hr) {
            float mx = -1e30f;
#pragma unroll
            for (int nt = 0; nt < 8; ++nt)
                mx = fmaxf(mx, fmaxf(sacc[nt][hr * 2], sacc[nt][hr * 2 + 1]));
            mx = fmaxf(mx, __shfl_xor_sync(0xffffffffu, mx, 1));
            mx = fmaxf(mx, __shfl_xor_sync(0xffffffffu, mx, 2));
            float mnew = fmaxf(mr[hr], mx);
            float alpha = __expf(mr[hr] - mnew);
            mr[hr] = mnew;
            float rs = 0.f;
#pragma unroll
            for (int nt = 0; nt < 8; ++nt) {
                float p0 = __expf(sacc[nt][hr * 2] - mnew);
                float p1 = __expf(sacc[nt][hr * 2 + 1] - mnew);
                sacc[nt][hr * 2] = p0; sacc[nt][hr * 2 + 1] = p1;
                rs += p0 + p1;
            }
            rs += __shfl_xor_sync(0xffffffffu, rs, 1);
            rs += __shfl_xor_sync(0xffffffffu, rs, 2);
            lr[hr] = lr[hr] * alpha + rs;
#pragma unroll
            for (int nt = 0; nt < 8; ++nt) {
                oacc[nt][hr * 2]     *= alpha;
                oacc[nt][hr * 2 + 1] *= alpha;
            }
        }

        // ---- O += P V (bf16x3; V frags per tile-pair via trans-ldmatrix) ----
#pragma unroll
        for (int kk = 0; kk < 4; ++kk) {
            uint32_t pa_h[4], pa_l[4];
            {
                float x0 = sacc[2 * kk][0],     x1 = sacc[2 * kk][1];
                float x2 = sacc[2 * kk][2],     x3 = sacc[2 * kk][3];
                float y0 = sacc[2 * kk + 1][0], y1 = sacc[2 * kk + 1][1];
                float y2 = sacc[2 * kk + 1][2], y3 = sacc[2 * kk + 1][3];
                pa_h[0] = pack_bf(x0, x1);
                pa_h[1] = pack_bf(x2, x3);
                pa_h[2] = pack_bf(y0, y1);
                pa_h[3] = pack_bf(y2, y3);
                bf162* ph = (bf162*)pa_h;
                pa_l[0] = pack_bf(x0 - __bfloat162float(ph[0].x), x1 - __bfloat162float(ph[0].y));
                pa_l[1] = pack_bf(x2 - __bfloat162float(ph[1].x), x3 - __bfloat162float(ph[1].y));
                pa_l[2] = pack_bf(y0 - __bfloat162float(ph[2].x), y1 - __bfloat162float(ph[2].y));
                pa_l[3] = pack_bf(y2 - __bfloat162float(ph[3].x), y3 - __bfloat162float(ph[3].y));
            }
#pragma unroll
            for (int p = 0; p < 4; ++p) {
                int jl = kk * 16 + ((lane >> 3) & 1) * 8 + (lane & 7);
                int ch = p * 2 + (lane >> 4);
                uint32_t pos = fpos(jl, ch);
                uint32_t fh[4], fl[4];
                ldsm_x4_t(fh, kb + 16384 + pos);
                ldsm_x4_t(fl, kb + 24576 + pos);
                uint32_t v0h[2] = {fh[0], fh[1]}, v1h[2] = {fh[2], fh[3]};
                uint32_t v0l[2] = {fl[0], fl[1]}, v1l[2] = {fl[2], fl[3]};
                mma16(oacc[2 * p],     pa_h, v0h);
                mma16(oacc[2 * p],     pa_h, v0l);
                mma16(oacc[2 * p],     pa_l, v0h);
                mma16(oacc[2 * p + 1], pa_h, v1h);
                mma16(oacc[2 * p + 1], pa_h, v1l);
                mma16(oacc[2 * p + 1], pa_l, v1h);
            }
        }

        CP_ASYNC_WAIT(0);
        __syncthreads();
    }

    int cr = lane >> 2, cc = (lane & 3) * 2;
#pragma unroll
    for (int hr = 0; hr < 2; ++hr) {
        int row = row0 + wid * 16 + cr + hr * 8;
        size_t base = (((size_t)split * G + g) * FROWS + row) * DHH;
#pragma unroll
        for (int nt = 0; nt < 8; ++nt) {
            *(float2*)&g_pO[base + nt * 8 + cc] =
                make_float2(oacc[nt][hr * 2], oacc[nt][hr * 2 + 1]);
        }
        if ((lane & 3) == 0) {
            size_t mi = ((size_t)split * G + g) * FROWS + row;
            g_pM[mi] = mr[hr];
            g_pL[mi] = lr[hr];
        }
    }
}

// =====================================================================
// Combine split-j partials -> o1 planes [b*513+row][h*64+c].
// =====================================================================
__global__ void combine_kernel()
{
    int idx = blockIdx.x * 256 + threadIdx.x;
    if (idx >= G * NQ * 32) return;
    int c = (idx & 31) * 2;
    int rem = idx >> 5;
    int row = rem % NQ, g = rem / NQ;
    int b = g >> 3, h = g & 7;

    float m[NSPLIT], l[NSPLIT];
    float M = -1e30f;
#pragma unroll
    for (int s = 0; s < NSPLIT; ++s) {
        size_t mi = ((size_t)s * G + g) * FROWS + row;
        m[s] = g_pM[mi]; l[s] = g_pL[mi];
        M = fmaxf(M, m[s]);
    }
    float den = 0.f;
    float w[NSPLIT];
#pragma unroll
    for (int s = 0; s < NSPLIT; ++s) {
        w[s] = __expf(m[s] - M);
        den += w[s] * l[s];
    }
    float inv = 1.f / den;
    float vx = 0.f, vy = 0.f;
#pragma unroll
    for (int s = 0; s < NSPLIT; ++s) {
        size_t mi = ((size_t)s * G + g) * FROWS + row;
        float2 o = *(const float2*)&g_pO[mi * DHH + c];
        vx += w[s] * o.x; vy += w[s] * o.y;
    }
    vx *= inv; vy *= inv;

    bf16 hx, lx, hy, ly;
    bsplit(vx, hx, lx); bsplit(vy, hy, ly);
    bf162 hh; hh.x = hx; hh.y = hy;
    bf162 ll; ll.x = lx; ll.y = ly;
    size_t o = (size_t)(b * 513 + row) * 512 + h * 64 + c;
    *(bf162*)&g_o1h[o] = hh;
    *(bf162*)&g_o1l[o] = ll;
}

// =====================================================================
// x splitter
// =====================================================================
__global__ void split_x_kernel(const float* __restrict__ X)
{
    int i = blockIdx.x * 256 + threadIdx.x;
    float4 v = ((const float4*)X)[i];
    bf16 h0, l0, h1, l1, h2, l2, h3, l3;
    bsplit(v.x, h0, l0); bsplit(v.y, h1, l1);
    bsplit(v.z, h2, l2); bsplit(v.w, h3, l3);
    bf162 a, b;
    a.x = h0; a.y = h1; b.x = h2; b.y = h3;
    ((bf162*)g_xh)[i * 2] = a; ((bf162*)g_xh)[i * 2 + 1] = b;
    a.x = l0; a.y = l1; b.x = l2; b.y = l3;
    ((bf162*)g_xl)[i * 2] = a; ((bf162*)g_xl)[i * 2 + 1] = b;
}

// =====================================================================
// W_qkv transpose + split: D[c][r] = split(S[r][c]), S=[512][2048].
// =====================================================================
__global__ void transpose_split(const float* __restrict__ S,
                                bf16* __restrict__ Dh, bf16* __restrict__ Dl,
                                int R, int C)
{
    __shared__ float t[32][33];
    int bx = blockIdx.x * 32, by = blockIdx.y * 32;
#pragma unroll
    for (int i = 0; i < 32; i += 8)
        t[threadIdx.y + i][threadIdx.x] =
            S[(size_t)(by + threadIdx.y + i) * C + bx + threadIdx.x];
    __syncthreads();
#pragma unroll
    for (int i = 0; i < 32; i += 8) {
        float v = t[threadIdx.x][threadIdx.y + i];
        bf16 h, l; bsplit(v, h, l);
        size_t o = (size_t)(bx + threadIdx.y + i) * R + by + threadIdx.x;
        Dh[o] = h; Dl[o] = l;
    }
}

// =====================================================================
// W_out transpose with out1/out2 row split remap.
// =====================================================================
__global__ void trans_wout(const float* __restrict__ W)
{
    __shared__ float t[32][33];
    int bx = blockIdx.x * 32, by = blockIdx.y * 32;
#pragma unroll
    for (int i = 0; i < 32; i += 8)
        t[threadIdx.y + i][threadIdx.x] =
            W[(size_t)(by + threadIdx.y + i) * 512 + bx + threadIdx.x];
    __syncthreads();
#pragma unroll
    for (int i = 0; i < 32; i += 8) {
        int c = bx + threadIdx.y + i;
        int r = by + threadIdx.x;
        float v = t[threadIdx.x][threadIdx.y + i];
        int h = r >> 7, cc = r & 127;
        bf16 hh, ll; bsplit(v, hh, ll);
        size_t o = (size_t)c * 512 + h * 64 + (cc & 63);
        if (cc < 64) { g_Wo1th[o] = hh; g_Wo1tl[o] = ll; }
        else         { g_Wo2th[o] = hh; g_Wo2tl[o] = ll; }
    }
}

// =====================================================================
// out2 decay scan.  grid (16 g, 8 chunks), 64 threads.
// =====================================================================
__global__ __launch_bounds__(64) void scan_kernel()
{
    extern __shared__ float sm[];
    float* buf = sm;
    float* sv  = sm + 256 * 64;

    int g = blockIdx.x, chunk = blockIdx.y;
    int b = g >> 3, h = g & 7;
    int c = threadIdx.x;
    const float r = RDEC;
    int i0 = chunk * 256;

    for (int q = (int)threadIdx.x; q < 448; q += 64) {
        int j = i0 - 96 + q;
        if (j >= 0 && j < NN) {
            float s = (1.0f - powf(r, (float)(j + 1)) + r - powf(r, (float)(NN - j)))
                      / (1.0f - r);
            sv[q] = 1.0f / s;
        }
    }
    __syncthreads();

    const float* T = g_t + (size_t)b * 2048 * 512 + h * 64 + c;

    int je = i0 + 255 + 96; if (je > NN - 1) je = NN - 1;
    float gg = 0.f;
    for (int j = je; j >= i0; --j) {
        float u = T[(size_t)j * 512] * sv[j - i0 + 96];
        gg = gg * r + u;
        if (j < i0 + 256) buf[(j - i0) * 64 + c] = gg;
    }

    int js = i0 - 96; if (js < 0) js = 0;
    float f = 0.f;
    for (int j = js; j < i0 + 256; ++j) {
        float u = T[(size_t)j * 512] * sv[j - i0 + 96];
        f = f * r + u;
        if (j >= i0) {
            float v = f + buf[(j - i0) * 64 + c] - u;
            bf16 hh, ll; bsplit(v, hh, ll);
            size_t o = (size_t)(b * 2048 + j) * 512 + h * 64 + c;
            g_o2h[o] = hh; g_o2l[o] = ll;
        }
    }
}

// =====================================================================
#define SM_QKV   (STAGES * 2 * (128 * 64 + 64 * 64))    // 73728 (BN=64)
#define SM_O1    (STAGES * 2 * (64 * 64 + 64 * 64))     // 49152
#define SM_OUT   (STAGES * 2 * (128 * 64 + 64 * 64))    // 73728
#define SM_FLASH (2 * 32768)                            // 65536 (Q reuses stage 0)
#define SM_SCAN  (256 * 64 * 4 + 448 * 4)               // 67328

extern "C" void kernel_launch(void* const* d_in, const int* in_sizes, int n_in,
                              void* d_out, int out_size)
{
    const float* x     = (const float*)d_in[0];   // [2,2048,512]
    const float* W_qkv = (const float*)d_in[1];   // [512,2048]
    const float* W_out = (const float*)d_in[2];   // [1024,512]
    const float* b_out = (const float*)d_in[3];   // [512]
    float* out = (float*)d_out;                   // [2,2048,512]

    bf16 *p_xh, *p_xl, *p_Wqth, *p_Wqtl;
    bf16 *p_Wo1th, *p_Wo1tl, *p_Wo2th, *p_Wo2tl;
    bf16 *p_o1h, *p_o1l, *p_o2h, *p_o2l;
    float *p_O1;
    cudaGetSymbolAddress((void**)&p_xh,    g_xh);
    cudaGetSymbolAddress((void**)&p_xl,    g_xl);
    cudaGetSymbolAddress((void**)&p_Wqth,  g_Wqth);
    cudaGetSymbolAddress((void**)&p_Wqtl,  g_Wqtl);
    cudaGetSymbolAddress((void**)&p_Wo1th, g_Wo1th);
    cudaGetSymbolAddress((void**)&p_Wo1tl, g_Wo1tl);
    cudaGetSymbolAddress((void**)&p_Wo2th, g_Wo2th);
    cudaGetSymbolAddress((void**)&p_Wo2tl, g_Wo2tl);
    cudaGetSymbolAddress((void**)&p_o1h,   g_o1h);
    cudaGetSymbolAddress((void**)&p_o1l,   g_o1l);
    cudaGetSymbolAddress((void**)&p_o2h,   g_o2h);
    cudaGetSymbolAddress((void**)&p_o2l,   g_o2l);
    cudaGetSymbolAddress((void**)&p_O1,    g_O1);

    static bool attr_done = false;
    if (!attr_done) {
        cudaFuncSetAttribute(bmma_gemm<128, 64, 1>,
                             cudaFuncAttributeMaxDynamicSharedMemorySize, SM_QKV);
        cudaFuncSetAttribute(bmma_gemm<64, 64, 0>,
                             cudaFuncAttributeMaxDynamicSharedMemorySize, SM_O1);
        cudaFuncSetAttribute(bmma_gemm<128, 64, 5>,
                             cudaFuncAttributeMaxDynamicSharedMemorySize, SM_OUT);
        cudaFuncSetAttribute(flash_kernel,
                             cudaFuncAttributeMaxDynamicSharedMemorySize, SM_FLASH);
        cudaFuncSetAttribute(scan_kernel,
                             cudaFuncAttributeMaxDynamicSharedMemorySize, SM_SCAN);
        attr_done = true;
    }

    // 0) input/weight plane production
    split_x_kernel<<<(ROWS * DIMM / 4) / 256, 256>>>(x);
    transpose_split<<<dim3(64, 16), dim3(32, 8)>>>(W_qkv, p_Wqth, p_Wqtl, 512, 2048);
    trans_wout<<<dim3(16, 32), dim3(32, 8)>>>(W_out);

    // 1) qkvt: Q (rows<640/batch) + K/V/t, fused plane epilogues.
    //    128x64 tiles: 848 active CTAs -> 2.86 waves at 2 CTA/SM (better balance).
    bmma_gemm<128, 64, 1><<<dim3(32, 32, 1), 256, SM_QKV>>>(
        p_xh, p_xl, DIMM, p_Wqth, p_Wqtl, DIMM, nullptr, 0, ROWS, DIMM, nullptr);

    // 2) fused flash (split-j x8, 640 CTAs) + combine -> o1 planes
    flash_kernel<<<dim3(NSPLIT, 5, G), 256, SM_FLASH>>>();
    combine_kernel<<<(G * NQ * 32 + 255) / 256, 256>>>();

    // 3) out2 decay scan -> o2 planes
    scan_kernel<<<dim3(G, 8), 64, SM_SCAN>>>();

    // 4) O1proj = o1 @ Wo1 : M=1026, N=512, K=512
    bmma_gemm<64, 64, 0><<<dim3(8, 17, 1), 256, SM_O1>>>(
        p_o1h, p_o1l, 512, p_Wo1th, p_Wo1tl, 512, p_O1, 512, 1026, 512, nullptr);

    // 5) out = o2 @ Wo2 + gather(O1proj) + b_out : M=4096, N=512, K=512
    bmma_gemm<128, 64, 5><<<dim3(8, 32, 1), 256, SM_OUT>>>(
        p_o2h, p_o2l, 512, p_Wo2th, p_Wo2tl, 512, out, DIMM, ROWS, 512, b_out);
}

// round 15
// speedup vs baseline: 1.1051x; 1.1051x over previous
#include <cuda_runtime.h>
#include <cuda_bf16.h>
#include <cstdint>
#include <cstddef>

// Problem constants
#define BB    2
#define NN    2048
#define DIMM  512
#define HH    8
#define DHH   64
#define NQ    513          // distinct effective query rows per head (q[i] = q[i % 513])
#define G     16           // B*H
#define ROWS  4096         // B*N
#define FROWS 640          // padded NQ for flash partials (5 * 128)
#define NSPLIT 4           // flash split-j factor

// r = exp(-1/e)
#define RDEC 0.69220062755534637f

typedef __nv_bfloat16  bf16;
typedef __nv_bfloat162 bf162;

// ---------------- scratch (static device arrays; no allocation) ----------------
__device__ __align__(256) float g_t[(size_t)ROWS * 512];          // t quarter fp32
__device__ __align__(256) float g_O1[(size_t)1152 * 512];         // O1proj fp32

__device__ __align__(256) bf16 g_xh[(size_t)ROWS * DIMM];         // x planes
__device__ __align__(256) bf16 g_xl[(size_t)ROWS * DIMM];
__device__ __align__(256) bf16 g_Wqth[(size_t)2048 * DIMM];       // W_qkv^T planes
__device__ __align__(256) bf16 g_Wqtl[(size_t)2048 * DIMM];
__device__ __align__(256) bf16 g_Wo1th[(size_t)512 * 512];        // W_out^T (out1 rows) planes
__device__ __align__(256) bf16 g_Wo1tl[(size_t)512 * 512];
__device__ __align__(256) bf16 g_Wo2th[(size_t)512 * 512];        // W_out^T (out2 rows) planes
__device__ __align__(256) bf16 g_Wo2tl[(size_t)512 * 512];
__device__ __align__(256) bf16 g_qkh[(size_t)ROWS * 1024];        // Q/K planes (cols 0..1023)
__device__ __align__(256) bf16 g_qkl[(size_t)ROWS * 1024];
__device__ __align__(256) bf16 g_vh[(size_t)ROWS * 512];          // V planes [row][h*64+c]
__device__ __align__(256) bf16 g_vl[(size_t)ROWS * 512];
__device__ __align__(256) bf16 g_o1h[(size_t)1152 * 512];         // combine out planes
__device__ __align__(256) bf16 g_o1l[(size_t)1152 * 512];
__device__ __align__(256) bf16 g_o2h[(size_t)ROWS * 512];         // scan out planes
__device__ __align__(256) bf16 g_o2l[(size_t)ROWS * 512];

// flash split-j partials
__device__ __align__(256) float g_pO[(size_t)NSPLIT * G * FROWS * DHH];
__device__ __align__(256) float g_pM[NSPLIT * G * FROWS];
__device__ __align__(256) float g_pL[NSPLIT * G * FROWS];

// ======================= portable PTX helpers =======================
__device__ __forceinline__ uint32_t smem_u32(const void* p) {
    uint32_t a;
    asm("{ .reg .u64 t; cvta.to.shared.u64 t, %1; cvt.u32.u64 %0, t; }" : "=r"(a) : "l"(p));
    return a;
}
__device__ __forceinline__ void ldsm_x4(uint32_t* f, uint32_t addr) {
    asm volatile("ldmatrix.sync.aligned.m8n8.x4.shared.b16 {%0,%1,%2,%3}, [%4];"
                 : "=r"(f[0]), "=r"(f[1]), "=r"(f[2]), "=r"(f[3]) : "r"(addr));
}
__device__ __forceinline__ void ldsm_x4_t(uint32_t* f, uint32_t addr) {
    asm volatile("ldmatrix.sync.aligned.m8n8.x4.trans.shared.b16 {%0,%1,%2,%3}, [%4];"
                 : "=r"(f[0]), "=r"(f[1]), "=r"(f[2]), "=r"(f[3]) : "r"(addr));
}
__device__ __forceinline__ void mma16(float* c, const uint32_t* a, const uint32_t* b) {
    asm volatile("mma.sync.aligned.m16n8k16.row.col.f32.bf16.bf16.f32 "
                 "{%0,%1,%2,%3}, {%4,%5,%6,%7}, {%8,%9}, {%0,%1,%2,%3};"
                 : "+f"(c[0]), "+f"(c[1]), "+f"(c[2]), "+f"(c[3])
                 : "r"(a[0]), "r"(a[1]), "r"(a[2]), "r"(a[3]), "r"(b[0]), "r"(b[1]));
}
#define CP_ASYNC_COMMIT() asm volatile("cp.async.commit_group;")
#define CP_ASYNC_WAIT(n)  asm volatile("cp.async.wait_group %0;" :: "n"(n))
#define CP_ASYNC16(dst, src) \
    asm volatile("cp.async.cg.shared.global [%0], [%1], 16;" :: "r"(dst), "l"(src))
#define CP_ASYNC16Z(dst, src, gz) \
    asm volatile("cp.async.cg.shared.global [%0], [%1], 16, %2;" :: "r"(dst), "l"(src), "r"(gz))

__device__ __forceinline__ void bsplit(float v, bf16& h, bf16& l) {
    h = __float2bfloat16(v);
    l = __float2bfloat16(v - __bfloat162float(h));
}
__device__ __forceinline__ uint32_t pack_bf(float lo, float hi) {
    bf162 t; t.x = __float2bfloat16(lo); t.y = __float2bfloat16(hi);
    return *(uint32_t*)&t;
}

// interleaved-line SMEM layout for BK=32 (64B rows): 2 rows per 128B line
__device__ __forceinline__ uint32_t tpos(int r, int ch) {
    return ((uint32_t)(r >> 1) << 7) |
           ((uint32_t)((((r & 1) << 2) | ch) ^ ((r >> 1) & 7)) << 4);
}
// full-line layout for 128B rows (64 bf16): chunk ch in 0..7
__device__ __forceinline__ uint32_t fpos(int r, int ch) {
    return ((uint32_t)r << 7) | ((uint32_t)(ch ^ (r & 7)) << 4);
}

#define STAGES 3

// =====================================================================
// bf16x3 mma.sync GEMM: C[M,N] = A[M,K] @ B[N,K]^T (+extras)
// A/B as (hi, lo) bf16 planes, K-major.  CTA BM x BN, 8 warps (4m x 2n).
// __launch_bounds__(256, 2): cap 128 regs -> 2 CTAs/SM.
// MODE 0: plain fp32 C (+bias if given).
// MODE 1: qkvt producer (Q region only rows%2048<640; fused plane epilogues).
// MODE 5: final out.  C = acc + bias[cg] + O1proj[b*513 + i%513][cg].
// =====================================================================
template<int BM, int BN, int MODE>
__global__ __launch_bounds__(256, 2) void bmma_gemm(
    const bf16* __restrict__ Ah, const bf16* __restrict__ Al, int lda,
    const bf16* __restrict__ Bh, const bf16* __restrict__ Bl, int ldb,
    float* __restrict__ C, int ldc,
    int M, int K, const float* __restrict__ bias)
{
    constexpr int MT     = BM / 64;
    constexpr int NTILES = BN / 16;
    constexpr int APL = BM * 64;
    constexpr int BPL = BN * 64;
    constexpr int STAGE = 2 * (APL + BPL);

    int row0 = blockIdx.y * BM;
    int col0 = blockIdx.x * BN;
    if (MODE == 1) {
        if (col0 < 512 && (row0 & 2047) >= FROWS) return;   // Q region: 640 rows/batch
    }

    extern __shared__ __align__(1024) char smem[];
    uint32_t sbase = smem_u32(smem);
    int tid = threadIdx.x, wid = tid >> 5, lane = tid & 31;

    auto load_stage = [&](int stage, int k0) {
        uint32_t sb = sbase + stage * STAGE;
#pragma unroll
        for (int i = 0; i < BM * 4 / 256; ++i) {
            int id = tid + i * 256;
            int r = id >> 2, ch = id & 3;
            uint32_t pos = tpos(r, ch);
            const bf16* sh = Ah + (size_t)(row0 + r) * lda + k0 + ch * 8;
            const bf16* sl = Al + (size_t)(row0 + r) * lda + k0 + ch * 8;
            uint32_t gz = (row0 + r < M) ? 16u : 0u;
            CP_ASYNC16Z(sb + pos, sh, gz);
            CP_ASYNC16Z(sb + APL + pos, sl, gz);
        }
#pragma unroll
        for (int i = 0; i < BN * 4 / 256; ++i) {
            int id = tid + i * 256;
            int r = id >> 2, ch = id & 3;
            uint32_t pos = tpos(r, ch);
            const bf16* sh = Bh + (size_t)(col0 + r) * ldb + k0 + ch * 8;
            const bf16* sl = Bl + (size_t)(col0 + r) * ldb + k0 + ch * 8;
            CP_ASYNC16(sb + 2 * APL + pos, sh);
            CP_ASYNC16(sb + 2 * APL + BPL + pos, sl);
        }
    };

    int NT = K >> 5;
#pragma unroll
    for (int s = 0; s < STAGES - 1; ++s) {
        if (s < NT) load_stage(s, s * 32);
        CP_ASYNC_COMMIT();
    }

    int wm = wid & 3, wn = wid >> 2;
    int mbase = wm * (BM / 4);
    int nbase = wn * (BN / 2);

    float acc[MT][NTILES][4];
#pragma unroll
    for (int mt = 0; mt < MT; ++mt)
#pragma unroll
        for (int nt = 0; nt < NTILES; ++nt)
#pragma unroll
            for (int j = 0; j < 4; ++j) acc[mt][nt][j] = 0.f;

    for (int t = 0; t < NT; ++t) {
        CP_ASYNC_WAIT(STAGES - 2);
        __syncthreads();
        if (t + STAGES - 1 < NT)
            load_stage((t + STAGES - 1) % STAGES, (t + STAGES - 1) * 32);
        CP_ASYNC_COMMIT();

        uint32_t sb = sbase + (t % STAGES) * STAGE;
#pragma unroll
        for (int kk = 0; kk < 2; ++kk) {
            uint32_t ah[MT][4], al[MT][4];
#pragma unroll
            for (int mt = 0; mt < MT; ++mt) {
                int r = mbase + mt * 16 + (lane & 15);
                int ch = kk * 2 + (lane >> 4);
                uint32_t pos = tpos(r, ch);
                ldsm_x4(ah[mt], sb + pos);
                ldsm_x4(al[mt], sb + APL + pos);
            }
            uint32_t bh[NTILES][2], bl[NTILES][2];
#pragma unroll
            for (int p = 0; p < NTILES / 2; ++p) {
                int r = nbase + p * 16 + ((lane >> 4) << 3) + (lane & 7);
                int ch = kk * 2 + ((lane >> 3) & 1);
                uint32_t pos = tpos(r, ch);
                uint32_t f[4];
                ldsm_x4(f, sb + 2 * APL + pos);
                bh[2 * p][0] = f[0]; bh[2 * p][1] = f[1];
                bh[2 * p + 1][0] = f[2]; bh[2 * p + 1][1] = f[3];
                ldsm_x4(f, sb + 2 * APL + BPL + pos);
                bl[2 * p][0] = f[0]; bl[2 * p][1] = f[1];
                bl[2 * p + 1][0] = f[2]; bl[2 * p + 1][1] = f[3];
            }
#pragma unroll
            for (int mt = 0; mt < MT; ++mt)
#pragma unroll
                for (int nt = 0; nt < NTILES; ++nt) {
                    mma16(acc[mt][nt], ah[mt], bh[nt]);
                    mma16(acc[mt][nt], ah[mt], bl[nt]);
                    mma16(acc[mt][nt], al[mt], bh[nt]);
                }
        }
    }
    CP_ASYNC_WAIT(0);

    int cr = lane >> 2, cc = (lane & 3) * 2;
#pragma unroll
    for (int mt = 0; mt < MT; ++mt) {
        int rgb = row0 + mbase + mt * 16 + cr;
#pragma unroll
        for (int nt = 0; nt < NTILES; ++nt) {
            int cg = col0 + nbase + nt * 8 + cc;
#pragma unroll
            for (int half = 0; half < 2; ++half) {
                int rg = rgb + half * 8;
                if (rg >= M) continue;
                float vx = acc[mt][nt][half * 2];
                float vy = acc[mt][nt][half * 2 + 1];
                if (MODE == 0) {
                    if (bias) {
                        float2 b2 = *(const float2*)(bias + cg);
                        vx += b2.x; vy += b2.y;
                    }
                    *(float2*)(C + (size_t)rg * ldc + cg) = make_float2(vx, vy);
                } else if (MODE == 5) {
                    float2 b2 = *(const float2*)(bias + cg);
                    int b = rg >> 11, i = rg & 2047;
                    int i513 = i % 513;
                    float2 o1 = *(const float2*)&g_O1[(size_t)(b * 513 + i513) * 512 + cg];
                    *(float2*)(C + (size_t)rg * ldc + cg) =
                        make_float2(vx + b2.x + o1.x, vy + b2.y + o1.y);
                } else { // MODE 1
                    if (cg < 1024) {
                        bf16 hx, lx, hy, ly;
                        bsplit(vx, hx, lx); bsplit(vy, hy, ly);
                        bf162 hh; hh.x = hx; hh.y = hy;
                        bf162 ll; ll.x = lx; ll.y = ly;
                        *(bf162*)&g_qkh[(size_t)rg * 1024 + cg] = hh;
                        *(bf162*)&g_qkl[(size_t)rg * 1024 + cg] = ll;
                    } else if (cg < 1536) {
                        bf16 hx, lx, hy, ly;
                        bsplit(vx, hx, lx); bsplit(vy, hy, ly);
                        bf162 hh; hh.x = hx; hh.y = hy;
                        bf162 ll; ll.x = lx; ll.y = ly;
                        *(bf162*)&g_vh[(size_t)rg * 512 + cg - 1024] = hh;
                        *(bf162*)&g_vl[(size_t)rg * 512 + cg - 1024] = ll;
                    } else {
                        *(float2*)&g_t[(size_t)rg * 512 + cg - 1536] = make_float2(vx, vy);
                    }
                }
            }
        }
    }
}

// =====================================================================
// Fused flash attention: S = 0.125 * Q K^T, online softmax, O = P V.
// grid (NSPLIT, 5, 16), 8 warps.  Q smem region reused by KV stages
// (64 KB total) + reg cap -> 2 CTAs/SM.
// =====================================================================
__global__ __launch_bounds__(256, 2) void flash_kernel()
{
    constexpr int JT = 2048 / (NSPLIT * 64);     // j-tiles per split
    extern __shared__ __align__(1024) char smem[];
    uint32_t sb = smem_u32(smem);

    int split = blockIdx.x, mtile = blockIdx.y, g = blockIdx.z;
    int b = g >> 3, h = g & 7;
    int row0 = mtile * 128;
    int tid = threadIdx.x, wid = tid >> 5, lane = tid & 31;

    const bf16* Qh = g_qkh + (size_t)b * 2048 * 1024 + h * 64;
    const bf16* Ql = g_qkl + (size_t)b * 2048 * 1024 + h * 64;
    const bf16* Kh = Qh + 512;
    const bf16* Kl = Ql + 512;
    const bf16* Vh = g_vh + (size_t)b * 2048 * 512 + h * 64;
    const bf16* Vl = g_vl + (size_t)b * 2048 * 512 + h * 64;

    // ---- Q tile load into stage-0 region (reused by KV afterwards) ----
    const uint32_t sQh = sb, sQl = sb + 16384;
#pragma unroll
    for (int i = 0; i < 4; ++i) {
        int id = tid + i * 256;
        int r = id >> 3, ch = id & 7;
        uint32_t pos = fpos(r, ch);
        uint32_t gz = (row0 + r < NQ) ? 16u : 0u;
        CP_ASYNC16Z(sQh + pos, Qh + (size_t)(row0 + r) * 1024 + ch * 8, gz);
        CP_ASYNC16Z(sQl + pos, Ql + (size_t)(row0 + r) * 1024 + ch * 8, gz);
    }
    CP_ASYNC_COMMIT();
    CP_ASYNC_WAIT(0);
    __syncthreads();

    // ---- Q fragments (held for whole loop) ----
    uint32_t qh[4][4], ql[4][4];
#pragma unroll
    for (int kk = 0; kk < 4; ++kk) {
        int r = wid * 16 + (lane & 15);
        uint32_t pos = fpos(r, 2 * kk + (lane >> 4));
        ldsm_x4(qh[kk], sQh + pos);
        ldsm_x4(ql[kk], sQl + pos);
    }
    __syncthreads();   // all warps done reading Q before KV overwrites

    int j0 = split * (2048 / NSPLIT);
    auto load_kv = [&](int stage, int jt) {
        uint32_t kb = sb + stage * 32768;
        int jb = j0 + jt * 64;
#pragma unroll
        for (int i = 0; i < 2; ++i) {
            int id = tid + i * 256;
            int r = id >> 3, ch = id & 7;
            uint32_t pos = fpos(r, ch);
            CP_ASYNC16(kb + pos,         Kh + (size_t)(jb + r) * 1024 + ch * 8);
            CP_ASYNC16(kb + 8192 + pos,  Kl + (size_t)(jb + r) * 1024 + ch * 8);
            CP_ASYNC16(kb + 16384 + pos, Vh + (size_t)(jb + r) * 512 + ch * 8);
            CP_ASYNC16(kb + 24576 + pos, Vl + (size_t)(jb + r) * 512 + ch * 8);
        }
    };
    load_kv(0, 0);
    CP_ASYNC_COMMIT();
    CP_ASYNC_WAIT(0);
    __syncthreads();

    float mr[2] = {-1e30f, -1e30f};
    float lr[2] = {0.f, 0.f};
    float oacc[8][4];
#pragma unroll
    for (int nt = 0; nt < 8; ++nt)
#pragma unroll
        for (int j = 0; j < 4; ++j) oacc[nt][j] = 0.f;

    for (int t = 0; t < JT; ++t) {
        if (t + 1 < JT) load_kv((t + 1) & 1, t + 1);
        CP_ASYNC_COMMIT();

        uint32_t kb = sb + (t & 1) * 32768;

        // ---- S = Q K^T (bf16x3), fragments per tile-pair ----
        float sacc[8][4];
#pragma unroll
        for (int nt = 0; nt < 8; ++nt)
#pragma unroll
            for (int j = 0; j < 4; ++j) sacc[nt][j] = 0.f;
#pragma unroll
        for (int kk = 0; kk < 4; ++kk) {
#pragma unroll
            for (int p = 0; p < 4; ++p) {
                int r = p * 16 + ((lane >> 4) << 3) + (lane & 7);
                uint32_t pos = fpos(r, 2 * kk + ((lane >> 3) & 1));
                uint32_t fh[4], fl[4];
                ldsm_x4(fh, kb + pos);
                ldsm_x4(fl, kb + 8192 + pos);
                uint32_t b0h[2] = {fh[0], fh[1]}, b1h[2] = {fh[2], fh[3]};
                uint32_t b0l[2] = {fl[0], fl[1]}, b1l[2] = {fl[2], fl[3]};
                mma16(sacc[2 * p],     qh[kk], b0h);
                mma16(sacc[2 * p],     qh[kk], b0l);
                mma16(sacc[2 * p],     ql[kk], b0h);
                mma16(sacc[2 * p + 1], qh[kk], b1h);
                mma16(sacc[2 * p + 1], qh[kk], b1l);
                mma16(sacc[2 * p + 1], ql[kk], b1h);
            }
        }

        // ---- scale + online softmax ----
#pragma unroll
        for (int nt = 0; nt < 8; ++nt)
#pragma unroll
            for (int j = 0; j < 4; ++j) sacc[nt][j] *= 0.125f;

#pragma unroll
        for (int hr = 0; hr < 2; ++hr) {
            float mx = -1e30f;
#pragma unroll
            for (int nt = 0; nt < 8; ++nt)
                mx = fmaxf(mx, fmaxf(sacc[nt][hr * 2], sacc[nt][hr * 2 + 1]));
            mx = fmaxf(mx, __shfl_xor_sync(0xffffffffu, mx, 1));
            mx = fmaxf(mx, __shfl_xor_sync(0xffffffffu, mx, 2));
            float mnew = fmaxf(mr[hr], mx);
            float alpha = __expf(mr[hr] - mnew);
            mr[hr] = mnew;
            float rs = 0.f;
#pragma unroll
            for (int nt = 0; nt < 8; ++nt) {
                float p0 = __expf(sacc[nt][hr * 2] - mnew);
                float p1 = __expf(sacc[nt][hr * 2 + 1] - mnew);
                sacc[nt][hr * 2] = p0; sacc[nt][hr * 2 + 1] = p1;
                rs += p0 + p1;
            }
            rs += __shfl_xor_sync(0xffffffffu, rs, 1);
            rs += __shfl_xor_sync(0xffffffffu, rs, 2);
            lr[hr] = lr[hr] * alpha + rs;
#pragma unroll
            for (int nt = 0; nt < 8; ++nt) {
                oacc[nt][hr * 2]     *= alpha;
                oacc[nt][hr * 2 + 1] *= alpha;
            }
        }

        // ---- O += P V (bf16x3; V frags per tile-pair via trans-ldmatrix) ----
#pragma unroll
        for (int kk = 0; kk < 4; ++kk) {
            uint32_t pa_h[4], pa_l[4];
            {
                float x0 = sacc[2 * kk][0],     x1 = sacc[2 * kk][1];
                float x2 = sacc[2 * kk][2],     x3 = sacc[2 * kk][3];
                float y0 = sacc[2 * kk + 1][0], y1 = sacc[2 * kk + 1][1];
                float y2 = sacc[2 * kk + 1][2], y3 = sacc[2 * kk + 1][3];
                pa_h[0] = pack_bf(x0, x1);
                pa_h[1] = pack_bf(x2, x3);
                pa_h[2] = pack_bf(y0, y1);
                pa_h[3] = pack_bf(y2, y3);
                bf162* ph = (bf162*)pa_h;
                pa_l[0] = pack_bf(x0 - __bfloat162float(ph[0].x), x1 - __bfloat162float(ph[0].y));
                pa_l[1] = pack_bf(x2 - __bfloat162float(ph[1].x), x3 - __bfloat162float(ph[1].y));
                pa_l[2] = pack_bf(y0 - __bfloat162float(ph[2].x), y1 - __bfloat162float(ph[2].y));
                pa_l[3] = pack_bf(y2 - __bfloat162float(ph[3].x), y3 - __bfloat162float(ph[3].y));
            }
#pragma unroll
            for (int p = 0; p < 4; ++p) {
                int jl = kk * 16 + ((lane >> 3) & 1) * 8 + (lane & 7);
                int ch = p * 2 + (lane >> 4);
                uint32_t pos = fpos(jl, ch);
                uint32_t fh[4], fl[4];
                ldsm_x4_t(fh, kb + 16384 + pos);
                ldsm_x4_t(fl, kb + 24576 + pos);
                uint32_t v0h[2] = {fh[0], fh[1]}, v1h[2] = {fh[2], fh[3]};
                uint32_t v0l[2] = {fl[0], fl[1]}, v1l[2] = {fl[2], fl[3]};
                mma16(oacc[2 * p],     pa_h, v0h);
                mma16(oacc[2 * p],     pa_h, v0l);
                mma16(oacc[2 * p],     pa_l, v0h);
                mma16(oacc[2 * p + 1], pa_h, v1h);
                mma16(oacc[2 * p + 1], pa_h, v1l);
                mma16(oacc[2 * p + 1], pa_l, v1h);
            }
        }

        CP_ASYNC_WAIT(0);
        __syncthreads();
    }

    int cr = lane >> 2, cc = (lane & 3) * 2;
#pragma unroll
    for (int hr = 0; hr < 2; ++hr) {
        int row = row0 + wid * 16 + cr + hr * 8;
        size_t base = (((size_t)split * G + g) * FROWS + row) * DHH;
#pragma unroll
        for (int nt = 0; nt < 8; ++nt) {
            *(float2*)&g_pO[base + nt * 8 + cc] =
                make_float2(oacc[nt][hr * 2], oacc[nt][hr * 2 + 1]);
        }
        if ((lane & 3) == 0) {
            size_t mi = ((size_t)split * G + g) * FROWS + row;
            g_pM[mi] = mr[hr];
            g_pL[mi] = lr[hr];
        }
    }
}

// =====================================================================
// Combine split-j partials -> o1 planes [b*513+row][h*64+c].
// =====================================================================
__global__ void combine_kernel()
{
    int idx = blockIdx.x * 256 + threadIdx.x;
    if (idx >= G * NQ * 32) return;
    int c = (idx & 31) * 2;
    int rem = idx >> 5;
    int row = rem % NQ, g = rem / NQ;
    int b = g >> 3, h = g & 7;

    float m[NSPLIT], l[NSPLIT];
    float M = -1e30f;
#pragma unroll
    for (int s = 0; s < NSPLIT; ++s) {
        size_t mi = ((size_t)s * G + g) * FROWS + row;
        m[s] = g_pM[mi]; l[s] = g_pL[mi];
        M = fmaxf(M, m[s]);
    }
    float den = 0.f;
    float w[NSPLIT];
#pragma unroll
    for (int s = 0; s < NSPLIT; ++s) {
        w[s] = __expf(m[s] - M);
        den += w[s] * l[s];
    }
    float inv = 1.f / den;
    float vx = 0.f, vy = 0.f;
#pragma unroll
    for (int s = 0; s < NSPLIT; ++s) {
        size_t mi = ((size_t)s * G + g) * FROWS + row;
        float2 o = *(const float2*)&g_pO[mi * DHH + c];
        vx += w[s] * o.x; vy += w[s] * o.y;
    }
    vx *= inv; vy *= inv;

    bf16 hx, lx, hy, ly;
    bsplit(vx, hx, lx); bsplit(vy, hy, ly);
    bf162 hh; hh.x = hx; hh.y = hy;
    bf162 ll; ll.x = lx; ll.y = ly;
    size_t o = (size_t)(b * 513 + row) * 512 + h * 64 + c;
    *(bf162*)&g_o1h[o] = hh;
    *(bf162*)&g_o1l[o] = ll;
}

// =====================================================================
// x splitter
// =====================================================================
__global__ void split_x_kernel(const float* __restrict__ X)
{
    int i = blockIdx.x * 256 + threadIdx.x;
    float4 v = ((const float4*)X)[i];
    bf16 h0, l0, h1, l1, h2, l2, h3, l3;
    bsplit(v.x, h0, l0); bsplit(v.y, h1, l1);
    bsplit(v.z, h2, l2); bsplit(v.w, h3, l3);
    bf162 a, b;
    a.x = h0; a.y = h1; b.x = h2; b.y = h3;
    ((bf162*)g_xh)[i * 2] = a; ((bf162*)g_xh)[i * 2 + 1] = b;
    a.x = l0; a.y = l1; b.x = l2; b.y = l3;
    ((bf162*)g_xl)[i * 2] = a; ((bf162*)g_xl)[i * 2 + 1] = b;
}

// =====================================================================
// W_qkv transpose + split: D[c][r] = split(S[r][c]), S=[512][2048].
// =====================================================================
__global__ void transpose_split(const float* __restrict__ S,
                                bf16* __restrict__ Dh, bf16* __restrict__ Dl,
                                int R, int C)
{
    __shared__ float t[32][33];
    int bx = blockIdx.x * 32, by = blockIdx.y * 32;
#pragma unroll
    for (int i = 0; i < 32; i += 8)
        t[threadIdx.y + i][threadIdx.x] =
            S[(size_t)(by + threadIdx.y + i) * C + bx + threadIdx.x];
    __syncthreads();
#pragma unroll
    for (int i = 0; i < 32; i += 8) {
        float v = t[threadIdx.x][threadIdx.y + i];
        bf16 h, l; bsplit(v, h, l);
        size_t o = (size_t)(bx + threadIdx.y + i) * R + by + threadIdx.x;
        Dh[o] = h; Dl[o] = l;
    }
}

// =====================================================================
// W_out transpose with out1/out2 row split remap.
// =====================================================================
__global__ void trans_wout(const float* __restrict__ W)
{
    __shared__ float t[32][33];
    int bx = blockIdx.x * 32, by = blockIdx.y * 32;
#pragma unroll
    for (int i = 0; i < 32; i += 8)
        t[threadIdx.y + i][threadIdx.x] =
            W[(size_t)(by + threadIdx.y + i) * 512 + bx + threadIdx.x];
    __syncthreads();
#pragma unroll
    for (int i = 0; i < 32; i += 8) {
        int c = bx + threadIdx.y + i;
        int r = by + threadIdx.x;
        float v = t[threadIdx.x][threadIdx.y + i];
        int h = r >> 7, cc = r & 127;
        bf16 hh, ll; bsplit(v, hh, ll);
        size_t o = (size_t)c * 512 + h * 64 + (cc & 63);
        if (cc < 64) { g_Wo1th[o] = hh; g_Wo1tl[o] = ll; }
        else         { g_Wo2th[o] = hh; g_Wo2tl[o] = ll; }
    }
}

// =====================================================================
// out2 decay scan.  grid (16 g, 8 chunks), 64 threads.
// =====================================================================
__global__ __launch_bounds__(64) void scan_kernel()
{
    extern __shared__ float sm[];
    float* buf = sm;
    float* sv  = sm + 256 * 64;

    int g = blockIdx.x, chunk = blockIdx.y;
    int b = g >> 3, h = g & 7;
    int c = threadIdx.x;
    const float r = RDEC;
    int i0 = chunk * 256;

    for (int q = (int)threadIdx.x; q < 448; q += 64) {
        int j = i0 - 96 + q;
        if (j >= 0 && j < NN) {
            float s = (1.0f - powf(r, (float)(j + 1)) + r - powf(r, (float)(NN - j)))
                      / (1.0f - r);
            sv[q] = 1.0f / s;
        }
    }
    __syncthreads();

    const float* T = g_t + (size_t)b * 2048 * 512 + h * 64 + c;

    int je = i0 + 255 + 96; if (je > NN - 1) je = NN - 1;
    float gg = 0.f;
    for (int j = je; j >= i0; --j) {
        float u = T[(size_t)j * 512] * sv[j - i0 + 96];
        gg = gg * r + u;
        if (j < i0 + 256) buf[(j - i0) * 64 + c] = gg;
    }

    int js = i0 - 96; if (js < 0) js = 0;
    float f = 0.f;
    for (int j = js; j < i0 + 256; ++j) {
        float u = T[(size_t)j * 512] * sv[j - i0 + 96];
        f = f * r + u;
        if (j >= i0) {
            float v = f + buf[(j - i0) * 64 + c] - u;
            bf16 hh, ll; bsplit(v, hh, ll);
            size_t o = (size_t)(b * 2048 + j) * 512 + h * 64 + c;
            g_o2h[o] = hh; g_o2l[o] = ll;
        }
    }
}

// =====================================================================
#define SM_QKV   (STAGES * 2 * (128 * 64 + 128 * 64))   // 98304
#define SM_O1    (STAGES * 2 * (64 * 64 + 64 * 64))     // 49152
#define SM_OUT   (STAGES * 2 * (128 * 64 + 64 * 64))    // 73728
#define SM_FLASH (2 * 32768)                            // 65536 (Q reuses stage 0)
#define SM_SCAN  (256 * 64 * 4 + 448 * 4)               // 67328

extern "C" void kernel_launch(void* const* d_in, const int* in_sizes, int n_in,
                              void* d_out, int out_size)
{
    const float* x     = (const float*)d_in[0];   // [2,2048,512]
    const float* W_qkv = (const float*)d_in[1];   // [512,2048]
    const float* W_out = (const float*)d_in[2];   // [1024,512]
    const float* b_out = (const float*)d_in[3];   // [512]
    float* out = (float*)d_out;                   // [2,2048,512]

    bf16 *p_xh, *p_xl, *p_Wqth, *p_Wqtl;
    bf16 *p_Wo1th, *p_Wo1tl, *p_Wo2th, *p_Wo2tl;
    bf16 *p_o1h, *p_o1l, *p_o2h, *p_o2l;
    float *p_O1;
    cudaGetSymbolAddress((void**)&p_xh,    g_xh);
    cudaGetSymbolAddress((void**)&p_xl,    g_xl);
    cudaGetSymbolAddress((void**)&p_Wqth,  g_Wqth);
    cudaGetSymbolAddress((void**)&p_Wqtl,  g_Wqtl);
    cudaGetSymbolAddress((void**)&p_Wo1th, g_Wo1th);
    cudaGetSymbolAddress((void**)&p_Wo1tl, g_Wo1tl);
    cudaGetSymbolAddress((void**)&p_Wo2th, g_Wo2th);
    cudaGetSymbolAddress((void**)&p_Wo2tl, g_Wo2tl);
    cudaGetSymbolAddress((void**)&p_o1h,   g_o1h);
    cudaGetSymbolAddress((void**)&p_o1l,   g_o1l);
    cudaGetSymbolAddress((void**)&p_o2h,   g_o2h);
    cudaGetSymbolAddress((void**)&p_o2l,   g_o2l);
    cudaGetSymbolAddress((void**)&p_O1,    g_O1);

    static cudaStream_t s1 = nullptr, s2 = nullptr;
    static cudaEvent_t eFork, eWout, eSplitX, eQkvt, eScan;
    static bool init_done = false;
    if (!init_done) {
        cudaStreamCreateWithFlags(&s1, cudaStreamNonBlocking);
        cudaStreamCreateWithFlags(&s2, cudaStreamNonBlocking);
        cudaEventCreateWithFlags(&eFork,   cudaEventDisableTiming);
        cudaEventCreateWithFlags(&eWout,   cudaEventDisableTiming);
        cudaEventCreateWithFlags(&eSplitX, cudaEventDisableTiming);
        cudaEventCreateWithFlags(&eQkvt,   cudaEventDisableTiming);
        cudaEventCreateWithFlags(&eScan,   cudaEventDisableTiming);
        cudaFuncSetAttribute(bmma_gemm<128, 128, 1>,
                             cudaFuncAttributeMaxDynamicSharedMemorySize, SM_QKV);
        cudaFuncSetAttribute(bmma_gemm<64, 64, 0>,
                             cudaFuncAttributeMaxDynamicSharedMemorySize, SM_O1);
        cudaFuncSetAttribute(bmma_gemm<128, 64, 5>,
                             cudaFuncAttributeMaxDynamicSharedMemorySize, SM_OUT);
        cudaFuncSetAttribute(flash_kernel,
                             cudaFuncAttributeMaxDynamicSharedMemorySize, SM_FLASH);
        cudaFuncSetAttribute(scan_kernel,
                             cudaFuncAttributeMaxDynamicSharedMemorySize, SM_SCAN);
        init_done = true;
    }

    // ---- fork side streams from the main (captured) stream ----
    cudaEventRecord(eFork, 0);
    cudaStreamWaitEvent(s1, eFork, 0);
    cudaStreamWaitEvent(s2, eFork, 0);

    // s1: W_out transpose (independent until O1proj)
    trans_wout<<<dim3(16, 32), dim3(32, 8), 0, s1>>>(W_out);
    cudaEventRecord(eWout, s1);

    // s2: x splitter (parallel with W_qkv transpose on main stream)
    split_x_kernel<<<(ROWS * DIMM / 4) / 256, 256, 0, s2>>>(x);
    cudaEventRecord(eSplitX, s2);

    // main: W_qkv transpose, then qkvt after x planes ready
    transpose_split<<<dim3(64, 16), dim3(32, 8)>>>(W_qkv, p_Wqth, p_Wqtl, 512, 2048);
    cudaStreamWaitEvent(0, eSplitX, 0);

    // 1) qkvt: Q (rows<640/batch) + K/V/t, fused plane epilogues.
    bmma_gemm<128, 128, 1><<<dim3(16, 32, 1), 256, SM_QKV>>>(
        p_xh, p_xl, DIMM, p_Wqth, p_Wqtl, DIMM, nullptr, 0, ROWS, DIMM, nullptr);
    cudaEventRecord(eQkvt, 0);

    // s2: out2 decay scan (parallel with flash/combine/O1proj)
    cudaStreamWaitEvent(s2, eQkvt, 0);
    scan_kernel<<<dim3(G, 8), 64, SM_SCAN, s2>>>();
    cudaEventRecord(eScan, s2);

    // main: fused flash (split-j x4) + combine -> o1 planes
    flash_kernel<<<dim3(NSPLIT, 5, G), 256, SM_FLASH>>>();
    combine_kernel<<<(G * NQ * 32 + 255) / 256, 256>>>();

    // main: O1proj = o1 @ Wo1 (needs Wo1 planes from s1)
    cudaStreamWaitEvent(0, eWout, 0);
    bmma_gemm<64, 64, 0><<<dim3(8, 17, 1), 256, SM_O1>>>(
        p_o1h, p_o1l, 512, p_Wo1th, p_Wo1tl, 512, p_O1, 512, 1026, 512, nullptr);

    // main: final out (needs o2 planes from s2)
    cudaStreamWaitEvent(0, eScan, 0);
    bmma_gemm<128, 64, 5><<<dim3(8, 32, 1), 256, SM_OUT>>>(
        p_o2h, p_o2l, 512, p_Wo2th, p_Wo2tl, 512, out, DIMM, ROWS, 512, b_out);
}